// round 9
// baseline (speedup 1.0000x reference)
#include <cuda_runtime.h>
#include <math_constants.h>
#include <stdint.h>

// WindowRouting: out[b,q,0:4] = (float)indices of top-4 over m of
// dot(Q[b,q,:], I[b,m,:]).  Positive scale cannot change ordering -> skipped.
// Shapes fixed: B=4, Nq=4096, M=8192, K=128.  OUTPUT DTYPE IS FLOAT32.
//
// R9 change: inner product uses packed fp32x2 FMA (fma.rn.f32x2, Blackwell
// FFMA2) — halves fp32 instruction count. Accumulators are packed 64-bit
// partials (lo=even k, hi=odd k), folded per tile. ulonglong2 smem loads give
// the packed operand pairs for free (same LDS.128 as float4).

#define KDIM 128
#define NB   4
#define NQ   4096
#define MM   8192
#define TQ   64
#define TM   128
#define NTH  256

__device__ __forceinline__ void ffma2(unsigned long long& acc,
                                      unsigned long long a,
                                      unsigned long long b)
{
    asm("fma.rn.f32x2 %0, %1, %2, %0;" : "+l"(acc) : "l"(a), "l"(b));
}

__global__ __launch_bounds__(NTH, 1)
void window_routing_tiled(const float* __restrict__ query,
                          const float* __restrict__ image,
                          float* __restrict__ out)
{
    extern __shared__ float4 smem4[];
    float4* Qs = smem4;              // TQ*32 float4 = 32 KB
    float4* Is = smem4 + TQ * 32;    // TM*32 float4 = 64 KB  (96 KB total)

    const int t  = threadIdx.x;
    const int tx = t & 15;           // m-direction
    const int ty = t >> 4;           // q-direction
    const int b  = blockIdx.y;
    const int q0 = blockIdx.x * TQ;

    const float* ibase = image + (size_t)b * MM * KDIM;

    // ---- load Q tile once (chunk c of row r stored at c ^ (r&7)) ----
    #pragma unroll
    for (int it = 0; it < (TQ * 32) / NTH; ++it) {
        int lin = it * NTH + t;
        int r = lin >> 5;
        int c = lin & 31;
        const float* src = query + ((size_t)b * NQ + (q0 + r)) * KDIM;
        Qs[r * 32 + (c ^ (r & 7))] = ((const float4*)src)[c];
    }

    // running top-4 per owned q-row (q = ty + 16*i, i<4)
    float topv[4][4];
    int   topi[4][4];
    #pragma unroll
    for (int i = 0; i < 4; ++i)
        #pragma unroll
        for (int s = 0; s < 4; ++s) { topv[i][s] = -CUDART_INF_F; topi[i][s] = 0x7FFFFFFF; }

    const int qsw = ty & 7;
    const int isw = tx & 7;

    const ulonglong2* Qs2 = (const ulonglong2*)Qs;
    const ulonglong2* Is2 = (const ulonglong2*)Is;

    for (int mt = 0; mt < MM; mt += TM) {
        __syncthreads();  // previous tile's reads done; also covers Q visibility
        #pragma unroll
        for (int it = 0; it < (TM * 32) / NTH; ++it) {
            int lin = it * NTH + t;
            int r = lin >> 5;
            int c = lin & 31;
            Is[r * 32 + (c ^ (r & 7))] = ((const float4*)(ibase + (size_t)(mt + r) * KDIM))[c];
        }
        __syncthreads();

        // packed accumulators: lo half = even-k partial, hi half = odd-k partial
        unsigned long long acc2[4][8];
        #pragma unroll
        for (int i = 0; i < 4; ++i)
            #pragma unroll
            for (int j = 0; j < 8; ++j) acc2[i][j] = 0ull;

        #pragma unroll 4
        for (int k4 = 0; k4 < 32; ++k4) {
            ulonglong2 qv[4], iv[8];
            #pragma unroll
            for (int i = 0; i < 4; ++i)
                qv[i] = Qs2[(ty + 16 * i) * 32 + (k4 ^ qsw)];
            #pragma unroll
            for (int j = 0; j < 8; ++j)
                iv[j] = Is2[(tx + 16 * j) * 32 + (k4 ^ isw)];
            #pragma unroll
            for (int i = 0; i < 4; ++i)
                #pragma unroll
                for (int j = 0; j < 8; ++j) {
                    ffma2(acc2[i][j], qv[i].x, iv[j].x);   // (k0,k1)
                    ffma2(acc2[i][j], qv[i].y, iv[j].y);   // (k2,k3)
                }
        }

        // fold: j ascending => m ascending; strict '>' keeps lowest index on ties
        #pragma unroll
        for (int j = 0; j < 8; ++j) {
            int mg = mt + tx + 16 * j;
            #pragma unroll
            for (int i = 0; i < 4; ++i) {
                unsigned long long p = acc2[i][j];
                float v = __int_as_float((unsigned)p) +
                          __int_as_float((unsigned)(p >> 32));
                if (v > topv[i][3]) {
                    topv[i][3] = v; topi[i][3] = mg;
                    #pragma unroll
                    for (int s = 3; s >= 1; --s) {
                        bool sw = (topv[i][s] > topv[i][s-1]) ||
                                  (topv[i][s] == topv[i][s-1] && topi[i][s] < topi[i][s-1]);
                        if (sw) {
                            float tv = topv[i][s]; topv[i][s] = topv[i][s-1]; topv[i][s-1] = tv;
                            int   ti = topi[i][s]; topi[i][s] = topi[i][s-1]; topi[i][s-1] = ti;
                        }
                    }
                }
            }
        }
    }

    // ---- cross-thread merge: 16 tx-threads x 4 candidates per q-row ----
    __syncthreads();
    float* cval = (float*)Qs;                 // TQ*16*4 floats = 16 KB
    int*   cidx = (int*)Qs + TQ * 16 * 4;     // next 16 KB (within Qs's 32 KB)

    #pragma unroll
    for (int i = 0; i < 4; ++i) {
        int q = ty + 16 * i;
        #pragma unroll
        for (int s = 0; s < 4; ++s) {
            cval[(q * 16 + tx) * 4 + s] = topv[i][s];
            cidx[(q * 16 + tx) * 4 + s] = topi[i][s];
        }
    }
    __syncthreads();

    if (t < TQ) {
        int q = t;
        int base = q * 64;
        int res[4];
        #pragma unroll
        for (int pick = 0; pick < 4; ++pick) {
            float best = -CUDART_INF_F;
            int bi = 0x7FFFFFFF, bc = 0;
            for (int c = 0; c < 64; ++c) {
                float v = cval[base + c];
                int   id = cidx[base + c];
                if (v > best || (v == best && id < bi)) { best = v; bi = id; bc = c; }
            }
            res[pick] = bi;
            cval[base + bc] = -CUDART_INF_F;
        }
        float* o = out + ((size_t)b * NQ + (q0 + q)) * 4;
        #pragma unroll
        for (int s = 0; s < 4; ++s) o[s] = (float)res[s];
    }
}

extern "C" void kernel_launch(void* const* d_in, const int* in_sizes, int n_in,
                              void* d_out, int out_size)
{
    (void)in_sizes; (void)n_in; (void)out_size;
    const float* query = (const float*)d_in[0];
    const float* image = (const float*)d_in[1];
    float* out = (float*)d_out;

    const int smem_bytes = (TQ * 32 + TM * 32) * (int)sizeof(float4);  // 96 KB
    cudaFuncSetAttribute(window_routing_tiled,
                         cudaFuncAttributeMaxDynamicSharedMemorySize, smem_bytes);

    dim3 grid(NQ / TQ, NB);   // (64, 4) = 256 blocks
    window_routing_tiled<<<grid, NTH, smem_bytes>>>(query, image, out);
}

// round 10
// speedup vs baseline: 1.1518x; 1.1518x over previous
#include <cuda_runtime.h>
#include <math_constants.h>
#include <stdint.h>

// WindowRouting: out[b,q,0:4] = (float)indices of top-4 over m of
// dot(Q[b,q,:], I[b,m,:]).  Positive scale cannot change ordering -> skipped.
// Shapes fixed: B=4, Nq=4096, M=8192, K=128.  OUTPUT DTYPE IS FLOAT32.
//
// R10 change: occupancy. 512 threads/CTA (16 warps = 4/SMSP, was 2/SMSP),
// per-thread tile 4q x 4m (~110 regs, fits 512thr in the regfile).
// Tile: TQ=128 x TM=64, K=128 in smem (Q 64KB + I 32KB = 96KB).
// FFMA2 packed fp32 math kept (halves issue pressure). XOR-swizzled LDS.128.

#define KDIM 128
#define NB   4
#define NQ   4096
#define MM   8192
#define TQ   128
#define TM   64
#define NTH  512

__device__ __forceinline__ void ffma2(unsigned long long& acc,
                                      unsigned long long a,
                                      unsigned long long b)
{
    asm("fma.rn.f32x2 %0, %1, %2, %0;" : "+l"(acc) : "l"(a), "l"(b));
}

__global__ __launch_bounds__(NTH, 1)
void window_routing_tiled(const float* __restrict__ query,
                          const float* __restrict__ image,
                          float* __restrict__ out)
{
    extern __shared__ float4 smem4[];
    float4* Qs = smem4;              // TQ*32 float4 = 64 KB
    float4* Is = smem4 + TQ * 32;    // TM*32 float4 = 32 KB  (96 KB total)

    const int t  = threadIdx.x;
    const int tx = t & 15;           // m-direction (16)
    const int ty = t >> 4;           // q-direction (32)
    const int b  = blockIdx.y;
    const int q0 = blockIdx.x * TQ;

    const float* ibase = image + (size_t)b * MM * KDIM;

    // ---- load Q tile once (chunk c of row r stored at c ^ (r&7)) ----
    #pragma unroll
    for (int it = 0; it < (TQ * 32) / NTH; ++it) {
        int lin = it * NTH + t;
        int r = lin >> 5;
        int c = lin & 31;
        const float* src = query + ((size_t)b * NQ + (q0 + r)) * KDIM;
        Qs[r * 32 + (c ^ (r & 7))] = ((const float4*)src)[c];
    }

    // running top-4 per owned q-row (q = ty + 32*i, i<4)
    float topv[4][4];
    int   topi[4][4];
    #pragma unroll
    for (int i = 0; i < 4; ++i)
        #pragma unroll
        for (int s = 0; s < 4; ++s) { topv[i][s] = -CUDART_INF_F; topi[i][s] = 0x7FFFFFFF; }

    const int qsw = ty & 7;
    const int isw = tx & 7;

    const ulonglong2* Qs2 = (const ulonglong2*)Qs;
    const ulonglong2* Is2 = (const ulonglong2*)Is;

    for (int mt = 0; mt < MM; mt += TM) {
        __syncthreads();  // previous tile's reads done; also covers Q visibility
        #pragma unroll
        for (int it = 0; it < (TM * 32) / NTH; ++it) {
            int lin = it * NTH + t;
            int r = lin >> 5;
            int c = lin & 31;
            Is[r * 32 + (c ^ (r & 7))] = ((const float4*)(ibase + (size_t)(mt + r) * KDIM))[c];
        }
        __syncthreads();

        // packed accumulators: lo = even-k partial, hi = odd-k partial
        unsigned long long acc2[4][4];
        #pragma unroll
        for (int i = 0; i < 4; ++i)
            #pragma unroll
            for (int j = 0; j < 4; ++j) acc2[i][j] = 0ull;

        #pragma unroll 4
        for (int k4 = 0; k4 < 32; ++k4) {
            ulonglong2 qv[4], iv[4];
            #pragma unroll
            for (int i = 0; i < 4; ++i)
                qv[i] = Qs2[(ty + 32 * i) * 32 + (k4 ^ qsw)];
            #pragma unroll
            for (int j = 0; j < 4; ++j)
                iv[j] = Is2[(tx + 16 * j) * 32 + (k4 ^ isw)];
            #pragma unroll
            for (int i = 0; i < 4; ++i)
                #pragma unroll
                for (int j = 0; j < 4; ++j) {
                    ffma2(acc2[i][j], qv[i].x, iv[j].x);   // (k0,k1)
                    ffma2(acc2[i][j], qv[i].y, iv[j].y);   // (k2,k3)
                }
        }

        // fold: j ascending => m ascending; strict '>' keeps lowest index on ties
        #pragma unroll
        for (int j = 0; j < 4; ++j) {
            int mg = mt + tx + 16 * j;
            #pragma unroll
            for (int i = 0; i < 4; ++i) {
                unsigned long long p = acc2[i][j];
                float v = __int_as_float((unsigned)p) +
                          __int_as_float((unsigned)(p >> 32));
                if (v > topv[i][3]) {
                    topv[i][3] = v; topi[i][3] = mg;
                    #pragma unroll
                    for (int s = 3; s >= 1; --s) {
                        bool sw = (topv[i][s] > topv[i][s-1]) ||
                                  (topv[i][s] == topv[i][s-1] && topi[i][s] < topi[i][s-1]);
                        if (sw) {
                            float tv = topv[i][s]; topv[i][s] = topv[i][s-1]; topv[i][s-1] = tv;
                            int   ti = topi[i][s]; topi[i][s] = topi[i][s-1]; topi[i][s-1] = ti;
                        }
                    }
                }
            }
        }
    }

    // ---- cross-thread merge: 16 tx-threads x 4 candidates per q-row ----
    __syncthreads();
    float* cval = (float*)Qs;                 // TQ*16*4 floats = 32 KB (in Qs)
    int*   cidx = (int*)Is;                   // TQ*16*4 ints  = 32 KB (in Is)

    #pragma unroll
    for (int i = 0; i < 4; ++i) {
        int q = ty + 32 * i;
        #pragma unroll
        for (int s = 0; s < 4; ++s) {
            cval[(q * 16 + tx) * 4 + s] = topv[i][s];
            cidx[(q * 16 + tx) * 4 + s] = topi[i][s];
        }
    }
    __syncthreads();

    if (t < TQ) {
        int q = t;
        int base = q * 64;
        int res[4];
        #pragma unroll
        for (int pick = 0; pick < 4; ++pick) {
            float best = -CUDART_INF_F;
            int bi = 0x7FFFFFFF, bc = 0;
            for (int c = 0; c < 64; ++c) {
                float v = cval[base + c];
                int   id = cidx[base + c];
                if (v > best || (v == best && id < bi)) { best = v; bi = id; bc = c; }
            }
            res[pick] = bi;
            cval[base + bc] = -CUDART_INF_F;
        }
        float* o = out + ((size_t)b * NQ + (q0 + q)) * 4;
        #pragma unroll
        for (int s = 0; s < 4; ++s) o[s] = (float)res[s];
    }
}

extern "C" void kernel_launch(void* const* d_in, const int* in_sizes, int n_in,
                              void* d_out, int out_size)
{
    (void)in_sizes; (void)n_in; (void)out_size;
    const float* query = (const float*)d_in[0];
    const float* image = (const float*)d_in[1];
    float* out = (float*)d_out;

    const int smem_bytes = (TQ * 32 + TM * 32) * (int)sizeof(float4);  // 96 KB
    cudaFuncSetAttribute(window_routing_tiled,
                         cudaFuncAttributeMaxDynamicSharedMemorySize, smem_bytes);

    dim3 grid(NQ / TQ, NB);   // (32, 4) = 128 blocks
    window_routing_tiled<<<grid, NTH, smem_bytes>>>(query, image, out);
}

// round 11
// speedup vs baseline: 1.9195x; 1.6665x over previous
#include <cuda_runtime.h>
#include <cuda_bf16.h>
#include <math_constants.h>
#include <stdint.h>

// WindowRouting: out[b,q,0:4] = (float)indices of top-4 over m of dot fp32.
// B=4, Nq=4096, M=8192, K=128. Output dtype float32.
//
// 3-stage pipeline:
//  1) convert: fp32 -> bf16 copies of Q and I (device-global scratch)
//  2) filter:  bf16 HMMA (mma.sync m16n8k16) scores; per-thread running top-8
//              over its disjoint m-column subset -> 32 candidates per q-row
//  3) rescore: exact fp32 dots for the 32 candidates, exact top-4 (ties: low idx)

#define KDIM 128
#define NB   4
#define NQ   4096
#define MM   8192
#define TOPT 8            // per-thread candidates in filter
#define NCAND 32          // 4 threads * TOPT per q-row

__device__ __nv_bfloat16 g_qb[NB * NQ * KDIM];    // 4 MB
__device__ __nv_bfloat16 g_ib[NB * MM * KDIM];    // 8 MB
__device__ int           g_cand[NB * NQ * NCAND]; // 2 MB

// ---------------- stage 1: fp32 -> bf16 ----------------
__global__ __launch_bounds__(256, 1)
void convert_kernel(const float* __restrict__ q, const float* __restrict__ im)
{
    const int idx  = blockIdx.x * 256 + threadIdx.x;   // one float4 per thread
    const int n_q4 = NB * NQ * KDIM / 4;               // 524288
    const int n_i4 = NB * MM * KDIM / 4;               // 1048576
    if (idx < n_q4) {
        float4 v = ((const float4*)q)[idx];
        __nv_bfloat162* d = (__nv_bfloat162*)g_qb;
        d[idx * 2 + 0] = __floats2bfloat162_rn(v.x, v.y);
        d[idx * 2 + 1] = __floats2bfloat162_rn(v.z, v.w);
    }
    if (idx < n_i4) {
        float4 v = ((const float4*)im)[idx];
        __nv_bfloat162* d = (__nv_bfloat162*)g_ib;
        d[idx * 2 + 0] = __floats2bfloat162_rn(v.x, v.y);
        d[idx * 2 + 1] = __floats2bfloat162_rn(v.z, v.w);
    }
}

// ---------------- stage 2: HMMA filter ----------------
// CTA: 256 thr = 8 warps; warp w owns q-rows q0 + 16w .. +15. Full K resident
// in A-fragments. I tiles of 128 rows staged in 32 KB smem (16B-chunk XOR swizzle).
__global__ __launch_bounds__(256, 1)
void filter_kernel()
{
    __shared__ __align__(16) __nv_bfloat16 Ish[128 * KDIM];   // 32 KB

    const int t    = threadIdx.x;
    const int lane = t & 31;
    const int w    = t >> 5;
    const int b    = blockIdx.y;
    const int q0   = blockIdx.x * 128;

    uint32_t sb;
    asm("{ .reg .u64 tt; cvta.to.shared.u64 tt, %1; cvt.u32.u64 %0, tt; }"
        : "=r"(sb) : "l"(Ish));

    // ---- A fragments: 16 q-rows x K=128, held in registers (8 k-tiles x 4 regs)
    const __nv_bfloat16* qb = g_qb + ((size_t)(b * NQ) + q0 + w * 16) * KDIM;
    const int gr = lane >> 2;           // fragment row group 0..7
    const int kq = (lane & 3) * 2;      // fragment k offset
    uint32_t A[8][4];
    #pragma unroll
    for (int kt = 0; kt < 8; ++kt) {
        A[kt][0] = *(const uint32_t*)(qb + (size_t)gr       * KDIM + kt * 16 + kq);
        A[kt][1] = *(const uint32_t*)(qb + (size_t)(gr + 8) * KDIM + kt * 16 + kq);
        A[kt][2] = *(const uint32_t*)(qb + (size_t)gr       * KDIM + kt * 16 + 8 + kq);
        A[kt][3] = *(const uint32_t*)(qb + (size_t)(gr + 8) * KDIM + kt * 16 + 8 + kq);
    }

    // running top-8 per owned row slot (slot0: row gr, slot1: row gr+8)
    float tv[2][TOPT];
    int   ti[2][TOPT];
    #pragma unroll
    for (int sl = 0; sl < 2; ++sl)
        #pragma unroll
        for (int s = 0; s < TOPT; ++s) { tv[sl][s] = -CUDART_INF_F; ti[sl][s] = 0; }

    const __nv_bfloat16* ibase = g_ib + (size_t)b * MM * KDIM;

    for (int mt = 0; mt < MM; mt += 128) {
        __syncthreads();
        // stage I tile: 128 rows x 16 chunks(16B); chunk c of row r at c^(r&7)
        #pragma unroll
        for (int it = 0; it < 8; ++it) {
            int lin = it * 256 + t;
            int r = lin >> 4;
            int c = lin & 15;
            ((uint4*)Ish)[r * 16 + (c ^ (r & 7))] =
                ((const uint4*)(ibase + (size_t)(mt + r) * KDIM))[c];
        }
        __syncthreads();

        #pragma unroll 2
        for (int sub = 0; sub < 16; ++sub) {      // 8 m-rows per subtile
            const int mrow = sub * 8 + (lane & 7);
            // 4x ldmatrix.x4 -> B fragments for all 16 k-chunks
            uint32_t bm[16];
            #pragma unroll
            for (int p = 0; p < 4; ++p) {
                uint32_t addr = sb +
                    (uint32_t)((mrow * 16 + ((p * 4 + (lane >> 3)) ^ (mrow & 7))) * 16);
                asm volatile(
                    "ldmatrix.sync.aligned.m8n8.x4.shared.b16 {%0,%1,%2,%3}, [%4];"
                    : "=r"(bm[p*4+0]), "=r"(bm[p*4+1]), "=r"(bm[p*4+2]), "=r"(bm[p*4+3])
                    : "r"(addr));
            }
            float c0 = 0.f, c1 = 0.f, c2 = 0.f, c3 = 0.f;
            #pragma unroll
            for (int s = 0; s < 8; ++s) {
                asm volatile(
                    "mma.sync.aligned.m16n8k16.row.col.f32.bf16.bf16.f32 "
                    "{%0,%1,%2,%3}, {%4,%5,%6,%7}, {%8,%9}, {%0,%1,%2,%3};"
                    : "+f"(c0), "+f"(c1), "+f"(c2), "+f"(c3)
                    : "r"(A[s][0]), "r"(A[s][1]), "r"(A[s][2]), "r"(A[s][3]),
                      "r"(bm[2*s]), "r"(bm[2*s+1]));
            }
            // fold: thread sees cols mc, mc+1 for both row slots
            const int mc = mt + sub * 8 + (lane & 3) * 2;
            #pragma unroll
            for (int e = 0; e < 4; ++e) {
                const float v  = (e == 0) ? c0 : (e == 1) ? c1 : (e == 2) ? c2 : c3;
                const int   sl = (e >> 1);
                const int   mg = mc + (e & 1);
                if (v > tv[sl][TOPT-1]) {
                    tv[sl][TOPT-1] = v; ti[sl][TOPT-1] = mg;
                    #pragma unroll
                    for (int s = TOPT - 1; s >= 1; --s) {
                        bool sw = (tv[sl][s] > tv[sl][s-1]) ||
                                  (tv[sl][s] == tv[sl][s-1] && ti[sl][s] < ti[sl][s-1]);
                        if (sw) {
                            float a = tv[sl][s]; tv[sl][s] = tv[sl][s-1]; tv[sl][s-1] = a;
                            int   i2 = ti[sl][s]; ti[sl][s] = ti[sl][s-1]; ti[sl][s-1] = i2;
                        }
                    }
                }
            }
        }
    }

    // write candidates: per row, quad (lane&3) owns slots [ (lane&3)*8 .. +7 ]
    const int row0 = b * NQ + q0 + w * 16 + gr;
    #pragma unroll
    for (int s = 0; s < TOPT; ++s) {
        g_cand[(size_t)row0      * NCAND + (lane & 3) * TOPT + s] = ti[0][s];
        g_cand[(size_t)(row0+8)  * NCAND + (lane & 3) * TOPT + s] = ti[1][s];
    }
}

// ---------------- stage 3: exact fp32 rescore ----------------
__global__ __launch_bounds__(256, 1)
void rescore_kernel(const float* __restrict__ q, const float* __restrict__ im,
                    float* __restrict__ out)
{
    const int lane = threadIdx.x & 31;
    const int w    = threadIdx.x >> 5;
    const int row  = blockIdx.x * 8 + w;          // 0 .. 16383
    const int b    = row >> 12;

    const float* qrow = q + (size_t)row * KDIM;
    const float q0 = qrow[lane];
    const float q1 = qrow[lane + 32];
    const float q2 = qrow[lane + 64];
    const float q3 = qrow[lane + 96];

    const float* ibase = im + (size_t)b * MM * KDIM;

    float vals[NCAND];
    int   idxs[NCAND];
    #pragma unroll
    for (int i = 0; i < NCAND; ++i) idxs[i] = g_cand[(size_t)row * NCAND + i];

    #pragma unroll 4
    for (int i = 0; i < NCAND; ++i) {
        const float* ir = ibase + (size_t)idxs[i] * KDIM;
        float p = q0 * ir[lane] + q1 * ir[lane + 32]
                + q2 * ir[lane + 64] + q3 * ir[lane + 96];
        p += __shfl_xor_sync(0xffffffffu, p, 16);
        p += __shfl_xor_sync(0xffffffffu, p, 8);
        p += __shfl_xor_sync(0xffffffffu, p, 4);
        p += __shfl_xor_sync(0xffffffffu, p, 2);
        p += __shfl_xor_sync(0xffffffffu, p, 1);
        vals[i] = p;   // identical on all lanes
    }

    if (lane == 0) {
        #pragma unroll
        for (int pick = 0; pick < 4; ++pick) {
            float best = -CUDART_INF_F; int bi = 0x7FFFFFFF, bc = 0;
            #pragma unroll
            for (int c = 0; c < NCAND; ++c) {
                if (vals[c] > best || (vals[c] == best && idxs[c] < bi)) {
                    best = vals[c]; bi = idxs[c]; bc = c;
                }
            }
            out[(size_t)row * 4 + pick] = (float)bi;
            vals[bc] = -CUDART_INF_F;
        }
    }
}

extern "C" void kernel_launch(void* const* d_in, const int* in_sizes, int n_in,
                              void* d_out, int out_size)
{
    (void)in_sizes; (void)n_in; (void)out_size;
    const float* query = (const float*)d_in[0];
    const float* image = (const float*)d_in[1];
    float* out = (float*)d_out;

    convert_kernel<<<(NB * MM * KDIM / 4 + 255) / 256, 256>>>(query, image);
    filter_kernel<<<dim3(NQ / 128, NB), 256>>>();
    rescore_kernel<<<(NB * NQ) / 8, 256>>>(query, image, out);
}

// round 12
// speedup vs baseline: 4.7829x; 2.4918x over previous
#include <cuda_runtime.h>
#include <cuda_bf16.h>
#include <math_constants.h>
#include <stdint.h>

// WindowRouting: out[b,q,0:4] = (float)indices of top-4 over m of fp32 dot.
// B=4, Nq=4096, M=8192, K=128. Output dtype float32.
//
// 3-stage: convert fp32->bf16; HMMA bf16 filter (top-4 per thread-subset,
// m-split across 2 CTAs -> 32 candidates/row); exact fp32 rescore.
// R12: m-split=2 (2 CTAs/SM -> 4 warps/SMSP) + 2 independent HMMA accumulator
// chains; fragment layouts identical to the R11-validated kernel.

#define KDIM 128
#define NB   4
#define NQ   4096
#define MM   8192
#define SPLIT 2
#define TOPT 4            // per-thread candidates in filter
#define NCAND 32          // SPLIT * 4 quads * TOPT

__device__ __nv_bfloat16 g_qb[NB * NQ * KDIM];    // 4 MB
__device__ __nv_bfloat16 g_ib[NB * MM * KDIM];    // 8 MB
__device__ int           g_cand[NB * NQ * NCAND]; // 2 MB

// ---------------- stage 1: fp32 -> bf16 ----------------
__global__ __launch_bounds__(256, 1)
void convert_kernel(const float* __restrict__ q, const float* __restrict__ im)
{
    const int idx  = blockIdx.x * 256 + threadIdx.x;
    const int n_q4 = NB * NQ * KDIM / 4;
    const int n_i4 = NB * MM * KDIM / 4;
    if (idx < n_q4) {
        float4 v = ((const float4*)q)[idx];
        __nv_bfloat162* d = (__nv_bfloat162*)g_qb;
        d[idx * 2 + 0] = __floats2bfloat162_rn(v.x, v.y);
        d[idx * 2 + 1] = __floats2bfloat162_rn(v.z, v.w);
    }
    if (idx < n_i4) {
        float4 v = ((const float4*)im)[idx];
        __nv_bfloat162* d = (__nv_bfloat162*)g_ib;
        d[idx * 2 + 0] = __floats2bfloat162_rn(v.x, v.y);
        d[idx * 2 + 1] = __floats2bfloat162_rn(v.z, v.w);
    }
}

// ---------------- stage 2: HMMA filter ----------------
// CTA: 256 thr = 8 warps; warp w owns q-rows q0+16w..+15; CTA scores m-range
// [z*4096, (z+1)*4096). I tiles of 128 rows in 32 KB smem (XOR-swizzled).
__global__ __launch_bounds__(256, 2)
void filter_kernel()
{
    __shared__ __align__(16) __nv_bfloat16 Ish[128 * KDIM];   // 32 KB

    const int t    = threadIdx.x;
    const int lane = t & 31;
    const int w    = t >> 5;
    const int b    = blockIdx.y;
    const int q0   = blockIdx.x * 128;
    const int z    = blockIdx.z;
    const int m0   = z * (MM / SPLIT);

    uint32_t sb;
    asm("{ .reg .u64 tt; cvta.to.shared.u64 tt, %1; cvt.u32.u64 %0, tt; }"
        : "=r"(sb) : "l"(Ish));

    // A fragments: 16 q-rows x K=128 (8 k-tiles x 4 regs) — layout as validated
    const __nv_bfloat16* qb = g_qb + ((size_t)(b * NQ) + q0 + w * 16) * KDIM;
    const int gr = lane >> 2;
    const int kq = (lane & 3) * 2;
    uint32_t A[8][4];
    #pragma unroll
    for (int kt = 0; kt < 8; ++kt) {
        A[kt][0] = *(const uint32_t*)(qb + (size_t)gr       * KDIM + kt * 16 + kq);
        A[kt][1] = *(const uint32_t*)(qb + (size_t)(gr + 8) * KDIM + kt * 16 + kq);
        A[kt][2] = *(const uint32_t*)(qb + (size_t)gr       * KDIM + kt * 16 + 8 + kq);
        A[kt][3] = *(const uint32_t*)(qb + (size_t)(gr + 8) * KDIM + kt * 16 + 8 + kq);
    }

    float tv[2][TOPT];
    int   ti[2][TOPT];
    #pragma unroll
    for (int sl = 0; sl < 2; ++sl)
        #pragma unroll
        for (int s = 0; s < TOPT; ++s) { tv[sl][s] = -CUDART_INF_F; ti[sl][s] = 0; }

    const __nv_bfloat16* ibase = g_ib + (size_t)b * MM * KDIM;

    for (int mt = m0; mt < m0 + MM / SPLIT; mt += 128) {
        __syncthreads();
        #pragma unroll
        for (int it = 0; it < 8; ++it) {
            int lin = it * 256 + t;
            int r = lin >> 4;
            int c = lin & 15;
            ((uint4*)Ish)[r * 16 + (c ^ (r & 7))] =
                ((const uint4*)(ibase + (size_t)(mt + r) * KDIM))[c];
        }
        __syncthreads();

        #pragma unroll 2
        for (int sub = 0; sub < 16; ++sub) {
            const int mrow = sub * 8 + (lane & 7);
            uint32_t bm[16];
            #pragma unroll
            for (int p = 0; p < 4; ++p) {
                uint32_t addr = sb +
                    (uint32_t)((mrow * 16 + ((p * 4 + (lane >> 3)) ^ (mrow & 7))) * 16);
                asm volatile(
                    "ldmatrix.sync.aligned.m8n8.x4.shared.b16 {%0,%1,%2,%3}, [%4];"
                    : "=r"(bm[p*4+0]), "=r"(bm[p*4+1]), "=r"(bm[p*4+2]), "=r"(bm[p*4+3])
                    : "r"(addr));
            }
            // two independent accumulate chains: k-tiles 0-3 and 4-7
            float a0 = 0.f, a1 = 0.f, a2 = 0.f, a3 = 0.f;
            float b0 = 0.f, b1 = 0.f, b2 = 0.f, b3 = 0.f;
            #pragma unroll
            for (int s = 0; s < 4; ++s) {
                asm volatile(
                    "mma.sync.aligned.m16n8k16.row.col.f32.bf16.bf16.f32 "
                    "{%0,%1,%2,%3}, {%4,%5,%6,%7}, {%8,%9}, {%0,%1,%2,%3};"
                    : "+f"(a0), "+f"(a1), "+f"(a2), "+f"(a3)
                    : "r"(A[s][0]), "r"(A[s][1]), "r"(A[s][2]), "r"(A[s][3]),
                      "r"(bm[2*s]), "r"(bm[2*s+1]));
                asm volatile(
                    "mma.sync.aligned.m16n8k16.row.col.f32.bf16.bf16.f32 "
                    "{%0,%1,%2,%3}, {%4,%5,%6,%7}, {%8,%9}, {%0,%1,%2,%3};"
                    : "+f"(b0), "+f"(b1), "+f"(b2), "+f"(b3)
                    : "r"(A[s+4][0]), "r"(A[s+4][1]), "r"(A[s+4][2]), "r"(A[s+4][3]),
                      "r"(bm[2*(s+4)]), "r"(bm[2*(s+4)+1]));
            }
            const float c0 = a0 + b0, c1 = a1 + b1, c2 = a2 + b2, c3 = a3 + b3;

            const int mc = mt + sub * 8 + (lane & 3) * 2;
            #pragma unroll
            for (int e = 0; e < 4; ++e) {
                const float v  = (e == 0) ? c0 : (e == 1) ? c1 : (e == 2) ? c2 : c3;
                const int   sl = (e >> 1);
                const int   mg = mc + (e & 1);
                if (v > tv[sl][TOPT-1]) {
                    tv[sl][TOPT-1] = v; ti[sl][TOPT-1] = mg;
                    #pragma unroll
                    for (int s = TOPT - 1; s >= 1; --s) {
                        bool sw = (tv[sl][s] > tv[sl][s-1]) ||
                                  (tv[sl][s] == tv[sl][s-1] && ti[sl][s] < ti[sl][s-1]);
                        if (sw) {
                            float aa = tv[sl][s]; tv[sl][s] = tv[sl][s-1]; tv[sl][s-1] = aa;
                            int   ii = ti[sl][s]; ti[sl][s] = ti[sl][s-1]; ti[sl][s-1] = ii;
                        }
                    }
                }
            }
        }
    }

    // candidates: [row][split z: 16][quad: 4][slot: TOPT]
    const int row0 = b * NQ + q0 + w * 16 + gr;
    #pragma unroll
    for (int s = 0; s < TOPT; ++s) {
        g_cand[(size_t)row0     * NCAND + z * 16 + (lane & 3) * TOPT + s] = ti[0][s];
        g_cand[(size_t)(row0+8) * NCAND + z * 16 + (lane & 3) * TOPT + s] = ti[1][s];
    }
}

// ---------------- stage 3: exact fp32 rescore ----------------
__global__ __launch_bounds__(256, 1)
void rescore_kernel(const float* __restrict__ q, const float* __restrict__ im,
                    float* __restrict__ out)
{
    const int lane = threadIdx.x & 31;
    const int w    = threadIdx.x >> 5;
    const int row  = blockIdx.x * 8 + w;
    const int b    = row >> 12;

    const float* qrow = q + (size_t)row * KDIM;
    const float q0 = qrow[lane];
    const float q1 = qrow[lane + 32];
    const float q2 = qrow[lane + 64];
    const float q3 = qrow[lane + 96];

    const float* ibase = im + (size_t)b * MM * KDIM;

    float vals[NCAND];
    int   idxs[NCAND];
    #pragma unroll
    for (int i = 0; i < NCAND; ++i) idxs[i] = g_cand[(size_t)row * NCAND + i];

    #pragma unroll 4
    for (int i = 0; i < NCAND; ++i) {
        const float* ir = ibase + (size_t)idxs[i] * KDIM;
        float p = q0 * ir[lane] + q1 * ir[lane + 32]
                + q2 * ir[lane + 64] + q3 * ir[lane + 96];
        p += __shfl_xor_sync(0xffffffffu, p, 16);
        p += __shfl_xor_sync(0xffffffffu, p, 8);
        p += __shfl_xor_sync(0xffffffffu, p, 4);
        p += __shfl_xor_sync(0xffffffffu, p, 2);
        p += __shfl_xor_sync(0xffffffffu, p, 1);
        vals[i] = p;
    }

    if (lane == 0) {
        #pragma unroll
        for (int pick = 0; pick < 4; ++pick) {
            float best = -CUDART_INF_F; int bi = 0x7FFFFFFF, bc = 0;
            #pragma unroll
            for (int c = 0; c < NCAND; ++c) {
                if (vals[c] > best || (vals[c] == best && idxs[c] < bi)) {
                    best = vals[c]; bi = idxs[c]; bc = c;
                }
            }
            out[(size_t)row * 4 + pick] = (float)bi;
            vals[bc] = -CUDART_INF_F;
        }
    }
}

extern "C" void kernel_launch(void* const* d_in, const int* in_sizes, int n_in,
                              void* d_out, int out_size)
{
    (void)in_sizes; (void)n_in; (void)out_size;
    const float* query = (const float*)d_in[0];
    const float* image = (const float*)d_in[1];
    float* out = (float*)d_out;

    convert_kernel<<<(NB * MM * KDIM / 4 + 255) / 256, 256>>>(query, image);
    filter_kernel<<<dim3(NQ / 128, NB, SPLIT), 256>>>();
    rescore_kernel<<<(NB * NQ) / 8, 256>>>(query, image, out);
}

// round 14
// speedup vs baseline: 4.8409x; 1.0121x over previous
#include <cuda_runtime.h>
#include <cuda_bf16.h>
#include <math_constants.h>
#include <stdint.h>

// WindowRouting: out[b,q,0:4] = (float)indices of top-4 over m of fp32 dot.
// B=4, Nq=4096, M=8192, K=128. Output float32.
// R14: mma.sync filter with (1) 128-thr CTAs / grid 512 -> all 148 SMs,
// (2) cp.async double-buffered I tiles (64 rows x 128 bf16, 2x16KB),
// (3) R12-identical fragment, fold, and candidate layouts. tcgen05 is
// unavailable (harness PTX target lacks the 'a' arch-variant features).

#define KDIM 128
#define NB   4
#define NQ   4096
#define MM   8192
#define SPLIT 2
#define TOPT 4
#define NCAND 32          // SPLIT * 4 quads * TOPT

__device__ __nv_bfloat16 g_qb[NB * NQ * KDIM];    // 4 MB
__device__ __nv_bfloat16 g_ib[NB * MM * KDIM];    // 8 MB
__device__ int           g_cand[NB * NQ * NCAND]; // 2 MB

// ---------------- stage 1: fp32 -> bf16 ----------------
__global__ __launch_bounds__(256, 1)
void convert_kernel(const float* __restrict__ q, const float* __restrict__ im)
{
    const int idx  = blockIdx.x * 256 + threadIdx.x;
    const int n_q4 = NB * NQ * KDIM / 4;
    const int n_i4 = NB * MM * KDIM / 4;
    if (idx < n_q4) {
        float4 v = ((const float4*)q)[idx];
        __nv_bfloat162* d = (__nv_bfloat162*)g_qb;
        d[idx * 2 + 0] = __floats2bfloat162_rn(v.x, v.y);
        d[idx * 2 + 1] = __floats2bfloat162_rn(v.z, v.w);
    }
    if (idx < n_i4) {
        float4 v = ((const float4*)im)[idx];
        __nv_bfloat162* d = (__nv_bfloat162*)g_ib;
        d[idx * 2 + 0] = __floats2bfloat162_rn(v.x, v.y);
        d[idx * 2 + 1] = __floats2bfloat162_rn(v.z, v.w);
    }
}

// ---------------- stage 2: HMMA filter ----------------
// CTA: 128 thr = 4 warps; warp w owns q-rows q0+16w..+15. CTA scores m-range
// [z*4096,(z+1)*4096) as 64 tiles of 64 m-rows, cp.async double-buffered.
#define NTILE 64
#define TROWS 64
#define TBYTES (TROWS * KDIM * 2)   // 16 KB

__device__ __forceinline__ uint32_t smem_u32(const void* p) {
    uint32_t a;
    asm("{ .reg .u64 tt; cvta.to.shared.u64 tt, %1; cvt.u32.u64 %0, tt; }"
        : "=r"(a) : "l"(p));
    return a;
}

__global__ __launch_bounds__(128, 4)
void filter_kernel()
{
    __shared__ __align__(1024) __nv_bfloat16 Ish[2][TROWS * KDIM];   // 2x16 KB

    const int t    = threadIdx.x;
    const int lane = t & 31;
    const int w    = t >> 5;
    const int b    = blockIdx.y;
    const int q0   = blockIdx.x * 64;
    const int z    = blockIdx.z;
    const int m0   = z * (MM / SPLIT);

    const uint32_t sb = smem_u32(&Ish[0][0]);

    // A fragments: 16 q-rows x K=128 (8 k-tiles x 4 regs) — validated layout
    const __nv_bfloat16* qb = g_qb + ((size_t)(b * NQ) + q0 + w * 16) * KDIM;
    const int gr = lane >> 2;
    const int kq = (lane & 3) * 2;
    uint32_t A[8][4];
    #pragma unroll
    for (int kt = 0; kt < 8; ++kt) {
        A[kt][0] = *(const uint32_t*)(qb + (size_t)gr       * KDIM + kt * 16 + kq);
        A[kt][1] = *(const uint32_t*)(qb + (size_t)(gr + 8) * KDIM + kt * 16 + kq);
        A[kt][2] = *(const uint32_t*)(qb + (size_t)gr       * KDIM + kt * 16 + 8 + kq);
        A[kt][3] = *(const uint32_t*)(qb + (size_t)(gr + 8) * KDIM + kt * 16 + 8 + kq);
    }

    float tv[2][TOPT];
    int   ti[2][TOPT];
    #pragma unroll
    for (int sl = 0; sl < 2; ++sl)
        #pragma unroll
        for (int s = 0; s < TOPT; ++s) { tv[sl][s] = -CUDART_INF_F; ti[sl][s] = 0; }

    const char* ibase = (const char*)(g_ib + ((size_t)b * MM + m0) * KDIM);

    // ---- cp.async tile stager: 8 chunks of 16B per thread
    auto stage = [&](int tile, int buf) {
        const char* src = ibase + (size_t)tile * TBYTES;
        #pragma unroll
        for (int i = 0; i < 8; ++i) {
            int lin = i * 128 + t;
            int r = lin >> 4;
            int c = lin & 15;
            uint32_t dst = sb + buf * TBYTES + r * 256 + ((c ^ (r & 7)) * 16);
            asm volatile("cp.async.cg.shared.global [%0], [%1], 16;"
                         :: "r"(dst), "l"(src + r * 256 + c * 16) : "memory");
        }
        asm volatile("cp.async.commit_group;" ::: "memory");
    };

    stage(0, 0);
    stage(1, 1);

    for (int it = 0; it < NTILE; ++it) {
        const int p = it & 1;
        if (it < NTILE - 1) asm volatile("cp.async.wait_group 1;" ::: "memory");
        else                asm volatile("cp.async.wait_group 0;" ::: "memory");
        __syncthreads();

        #pragma unroll 2
        for (int sub = 0; sub < 8; ++sub) {
            const int mrow = sub * 8 + (lane & 7);
            uint32_t bm[16];
            #pragma unroll
            for (int pp = 0; pp < 4; ++pp) {
                uint32_t addr = sb + p * TBYTES +
                    (uint32_t)((mrow * 16 + ((pp * 4 + (lane >> 3)) ^ (mrow & 7))) * 16);
                asm volatile(
                    "ldmatrix.sync.aligned.m8n8.x4.shared.b16 {%0,%1,%2,%3}, [%4];"
                    : "=r"(bm[pp*4+0]), "=r"(bm[pp*4+1]), "=r"(bm[pp*4+2]), "=r"(bm[pp*4+3])
                    : "r"(addr));
            }
            float a0 = 0.f, a1 = 0.f, a2 = 0.f, a3 = 0.f;
            float b0 = 0.f, b1 = 0.f, b2 = 0.f, b3 = 0.f;
            #pragma unroll
            for (int s = 0; s < 4; ++s) {
                asm volatile(
                    "mma.sync.aligned.m16n8k16.row.col.f32.bf16.bf16.f32 "
                    "{%0,%1,%2,%3}, {%4,%5,%6,%7}, {%8,%9}, {%0,%1,%2,%3};"
                    : "+f"(a0), "+f"(a1), "+f"(a2), "+f"(a3)
                    : "r"(A[s][0]), "r"(A[s][1]), "r"(A[s][2]), "r"(A[s][3]),
                      "r"(bm[2*s]), "r"(bm[2*s+1]));
                asm volatile(
                    "mma.sync.aligned.m16n8k16.row.col.f32.bf16.bf16.f32 "
                    "{%0,%1,%2,%3}, {%4,%5,%6,%7}, {%8,%9}, {%0,%1,%2,%3};"
                    : "+f"(b0), "+f"(b1), "+f"(b2), "+f"(b3)
                    : "r"(A[s+4][0]), "r"(A[s+4][1]), "r"(A[s+4][2]), "r"(A[s+4][3]),
                      "r"(bm[2*(s+4)]), "r"(bm[2*(s+4)+1]));
            }
            const float c0 = a0 + b0, c1 = a1 + b1, c2 = a2 + b2, c3 = a3 + b3;

            const int mc = m0 + it * TROWS + sub * 8 + (lane & 3) * 2;
            #pragma unroll
            for (int e = 0; e < 4; ++e) {
                const float v  = (e == 0) ? c0 : (e == 1) ? c1 : (e == 2) ? c2 : c3;
                const int   sl = (e >> 1);
                const int   mg = mc + (e & 1);
                if (v > tv[sl][TOPT-1]) {
                    tv[sl][TOPT-1] = v; ti[sl][TOPT-1] = mg;
                    #pragma unroll
                    for (int s = TOPT - 1; s >= 1; --s) {
                        bool sw = (tv[sl][s] > tv[sl][s-1]) ||
                                  (tv[sl][s] == tv[sl][s-1] && ti[sl][s] < ti[sl][s-1]);
                        if (sw) {
                            float aa = tv[sl][s]; tv[sl][s] = tv[sl][s-1]; tv[sl][s-1] = aa;
                            int   ii = ti[sl][s]; ti[sl][s] = ti[sl][s-1]; ti[sl][s-1] = ii;
                        }
                    }
                }
            }
        }
        __syncthreads();   // all warps done with buf p before restaging it
        if (it + 2 < NTILE) stage(it + 2, p);
    }

    // candidates: [row][z*16 + quad*4 + slot]  (identical to R12)
    const int row0 = b * NQ + q0 + w * 16 + gr;
    #pragma unroll
    for (int s = 0; s < TOPT; ++s) {
        g_cand[(size_t)row0     * NCAND + z * 16 + (lane & 3) * TOPT + s] = ti[0][s];
        g_cand[(size_t)(row0+8) * NCAND + z * 16 + (lane & 3) * TOPT + s] = ti[1][s];
    }
}

// ---------------- stage 3: exact fp32 rescore ----------------
__global__ __launch_bounds__(256, 1)
void rescore_kernel(const float* __restrict__ q, const float* __restrict__ im,
                    float* __restrict__ out)
{
    const int lane = threadIdx.x & 31;
    const int w    = threadIdx.x >> 5;
    const int row  = blockIdx.x * 8 + w;
    const int b    = row >> 12;

    const float* qrow = q + (size_t)row * KDIM;
    const float q0 = qrow[lane];
    const float q1 = qrow[lane + 32];
    const float q2 = qrow[lane + 64];
    const float q3 = qrow[lane + 96];

    const float* ibase = im + (size_t)b * MM * KDIM;

    float vals[NCAND];
    int   idxs[NCAND];
    #pragma unroll
    for (int i = 0; i < NCAND; ++i) idxs[i] = g_cand[(size_t)row * NCAND + i];

    #pragma unroll 4
    for (int i = 0; i < NCAND; ++i) {
        const float* ir = ibase + (size_t)idxs[i] * KDIM;
        float p = q0 * ir[lane] + q1 * ir[lane + 32]
                + q2 * ir[lane + 64] + q3 * ir[lane + 96];
        p += __shfl_xor_sync(0xffffffffu, p, 16);
        p += __shfl_xor_sync(0xffffffffu, p, 8);
        p += __shfl_xor_sync(0xffffffffu, p, 4);
        p += __shfl_xor_sync(0xffffffffu, p, 2);
        p += __shfl_xor_sync(0xffffffffu, p, 1);
        vals[i] = p;
    }

    if (lane == 0) {
        #pragma unroll
        for (int pick = 0; pick < 4; ++pick) {
            float best = -CUDART_INF_F; int bi = 0x7FFFFFFF, bc = 0;
            #pragma unroll
            for (int c = 0; c < NCAND; ++c) {
                if (vals[c] > best || (vals[c] == best && idxs[c] < bi)) {
                    best = vals[c]; bi = idxs[c]; bc = c;
                }
            }
            out[(size_t)row * 4 + pick] = (float)bi;
            vals[bc] = -CUDART_INF_F;
        }
    }
}

extern "C" void kernel_launch(void* const* d_in, const int* in_sizes, int n_in,
                              void* d_out, int out_size)
{
    (void)in_sizes; (void)n_in; (void)out_size;
    const float* query = (const float*)d_in[0];
    const float* image = (const float*)d_in[1];
    float* out = (float*)d_out;

    convert_kernel<<<(NB * MM * KDIM / 4 + 255) / 256, 256>>>(query, image);
    filter_kernel<<<dim3(NQ / 64, NB, SPLIT), 128>>>();
    rescore_kernel<<<(NB * NQ) / 8, 256>>>(query, image, out);
}